// round 5
// baseline (speedup 1.0000x reference)
#include <cuda_runtime.h>
#include <cuda_bf16.h>
#include <mma.h>
#include <stdint.h>
#include <math.h>

using namespace nvcuda;

#define SEQ 2048
#define DIM 4096
#define NH 32
#define NKV 8
#define HD 128
#define KVD (NKV*HD)   // 1024

typedef __nv_bfloat16 bf16;

// ================= scratch (no cudaMalloc allowed) =================
__device__ float g_scores[(size_t)NH * SEQ * SEQ];              // 512 MB
__device__ bf16 g_xh[SEQ * DIM],  g_xl[SEQ * DIM];
__device__ bf16 g_wqh[DIM * DIM], g_wql[DIM * DIM];
__device__ bf16 g_wkh[KVD * DIM], g_wkl[KVD * DIM];
__device__ bf16 g_wvh[KVD * DIM], g_wvl[KVD * DIM];
__device__ bf16 g_woh[DIM * DIM], g_wol[DIM * DIM];
__device__ bf16 g_qh[SEQ * DIM],  g_ql[SEQ * DIM];
__device__ bf16 g_kh[SEQ * KVD],  g_kl[SEQ * KVD];
__device__ bf16 g_vth[KVD * SEQ], g_vtl[KVD * SEQ];             // V transposed [d, t]
__device__ bf16 g_ph[(size_t)NH * SEQ * SEQ], g_pl[(size_t)NH * SEQ * SEQ];
__device__ bf16 g_ah[SEQ * DIM],  g_al[SEQ * DIM];

// ================= cp.async helpers =================
__device__ __forceinline__ void cpa16(uint32_t dst, const void* src) {
    unsigned long long g = (unsigned long long)__cvta_generic_to_global(src);
    asm volatile("cp.async.cg.shared.global [%0], [%1], 16;" :: "r"(dst), "l"(g) : "memory");
}
#define CPA_COMMIT() asm volatile("cp.async.commit_group;" ::: "memory")
#define CPA_WAIT(n)  asm volatile("cp.async.wait_group %0;" :: "n"(n) : "memory")

__device__ __forceinline__ void split2(float v0, float v1, bf16* ph, bf16* pl) {
    bf16 h0 = __float2bfloat16(v0), h1 = __float2bfloat16(v1);
    bf16 l0 = __float2bfloat16(v0 - __bfloat162float(h0));
    bf16 l1 = __float2bfloat16(v1 - __bfloat162float(h1));
    *(__nv_bfloat162*)ph = __halves2bfloat162(h0, h1);
    *(__nv_bfloat162*)pl = __halves2bfloat162(l0, l1);
}

// ================= 3-pass bf16 HMMA GEMM =================
// C[M,N] = Ah*Bh^T + Ah*Bl^T + Al*Bh^T   (TN, row-major, 128x128 CTA tiles)
// MODE 0: generic fp32 C.
// MODE 1: scores (per-head, causal tile skip), fp32 C.
// MODE 2: PV (per-head, K truncated at diagonal), bf16 hi/lo C.
// MODE 3: projection + RoPE + bf16 hi/lo C (Q and K projections).
// MODE 4: projection + transpose + bf16 hi/lo C (V projection).
//
// smem: TRIPLE-buffered chunks of K=32.  Each chunk holds 4 tiles
// (Ah, Al, Bh, Bl), each 128 rows x 32 bf16 with row stride 40 (80B).
#define TSTRIDE 40
#define TILE_E  (128 * TSTRIDE)          // 5120 elements per tile
#define CHUNK_E (4 * TILE_E)             // 20480 elements per buffer (40KB)
#define GSMEM   (3 * CHUNK_E * 2)        // 122880 bytes (>= 67584 staging)
#define SSTR    132                      // fp32 staging stride

template<int MODE>
__global__ void __launch_bounds__(256) gemm3_kernel(
    const bf16* __restrict__ Ah, const bf16* __restrict__ Al,
    const bf16* __restrict__ Bh, const bf16* __restrict__ Bl,
    float* __restrict__ Cf, bf16* __restrict__ Ch, bf16* __restrict__ Cl,
    int K, int lda, int ldb, int ldc)
{
    const int m0 = blockIdx.y * 128;
    const int n0 = blockIdx.x * 128;
    if (MODE == 1 && n0 > m0) return;   // tile fully above diagonal
    const int h = blockIdx.z, kvh = h >> 2;
    const int tid = threadIdx.x;
    const int warp = tid >> 5;
    const int wm = warp >> 1;           // 0..3  (32-row slice)
    const int wn = warp & 1;            // 0..1  (64-col slice)

    size_t aoff, boff, coff = 0;
    int kLen = K;
    if (MODE == 1)      { aoff = (size_t)m0 * lda + (size_t)h * HD;        boff = (size_t)n0 * ldb + (size_t)kvh * HD;
                          coff = (size_t)h * SEQ * SEQ; }
    else if (MODE == 2) { aoff = (size_t)h * SEQ * SEQ + (size_t)m0 * lda; boff = (size_t)(kvh * HD) * ldb;
                          kLen = m0 + 128; }
    else                { aoff = (size_t)m0 * lda;                         boff = (size_t)n0 * ldb; }
    const bf16* pAh = Ah + aoff; const bf16* pAl = Al + aoff;
    const bf16* pBh = Bh + boff; const bf16* pBl = Bl + boff;

    extern __shared__ __align__(16) char dsm[];
    bf16* smem = (bf16*)dsm;
    const uint32_t sm_u32 = (uint32_t)__cvta_generic_to_shared(dsm);

    wmma::fragment<wmma::accumulator, 16, 16, 16, float> acc[2][4];
    #pragma unroll
    for (int i = 0; i < 2; i++)
        #pragma unroll
        for (int j = 0; j < 4; j++) wmma::fill_fragment(acc[i][j], 0.0f);

    const int NC = kLen >> 5;   // K chunks of 32  (always >= 4 here)

    const int lrow = tid >> 1;
    const int lseg = (tid & 1) * 2;

    auto load_chunk = [&](int buf, int ko) {
        const uint32_t b = sm_u32 + buf * CHUNK_E * 2;
        const uint32_t soff = (uint32_t)(lrow * TSTRIDE + lseg * 8) * 2;
        const bf16* srcs[4] = { pAh + ko, pAl + ko, pBh + ko, pBl + ko };
        const int lds[4] = { lda, lda, ldb, ldb };
        #pragma unroll
        for (int t = 0; t < 4; t++) {
            const bf16* g = srcs[t] + (size_t)lrow * lds[t] + lseg * 8;
            const uint32_t d = b + t * TILE_E * 2 + soff;
            cpa16(d, g);
            cpa16(d + 16, g + 8);
        }
    };

    load_chunk(0, 0);  CPA_COMMIT();
    load_chunk(1, 32); CPA_COMMIT();

    for (int c = 0; c < NC; ++c) {
        if (c == NC - 1) { CPA_WAIT(0); } else { CPA_WAIT(1); }
        __syncthreads();
        if (c + 2 < NC) { load_chunk((c + 2) % 3, (c + 2) << 5); CPA_COMMIT(); }

        const bf16* sb = smem + (c % 3) * CHUNK_E;
        const bf16* sAh = sb;
        const bf16* sAl = sb + TILE_E;
        const bf16* sBh = sb + 2 * TILE_E;
        const bf16* sBl = sb + 3 * TILE_E;

        #pragma unroll
        for (int kk = 0; kk < 32; kk += 16) {
            wmma::fragment<wmma::matrix_a, 16, 16, 16, bf16, wmma::row_major> ah[2], al[2];
            wmma::fragment<wmma::matrix_b, 16, 16, 16, bf16, wmma::col_major> bh[4], bl[4];
            #pragma unroll
            for (int i = 0; i < 2; i++) {
                wmma::load_matrix_sync(ah[i], sAh + (wm * 32 + i * 16) * TSTRIDE + kk, TSTRIDE);
                wmma::load_matrix_sync(al[i], sAl + (wm * 32 + i * 16) * TSTRIDE + kk, TSTRIDE);
            }
            #pragma unroll
            for (int j = 0; j < 4; j++) {
                wmma::load_matrix_sync(bh[j], sBh + (wn * 64 + j * 16) * TSTRIDE + kk, TSTRIDE);
                wmma::load_matrix_sync(bl[j], sBl + (wn * 64 + j * 16) * TSTRIDE + kk, TSTRIDE);
            }
            #pragma unroll
            for (int i = 0; i < 2; i++)
                #pragma unroll
                for (int j = 0; j < 4; j++) {
                    wmma::mma_sync(acc[i][j], ah[i], bh[j], acc[i][j]);
                    wmma::mma_sync(acc[i][j], ah[i], bl[j], acc[i][j]);
                    wmma::mma_sync(acc[i][j], al[i], bh[j], acc[i][j]);
                }
        }
        __syncthreads();
    }

    // ===================== epilogues =====================
    if (MODE == 0 || MODE == 1) {
        float* C = Cf + coff;
        #pragma unroll
        for (int i = 0; i < 2; i++)
            #pragma unroll
            for (int j = 0; j < 4; j++)
                wmma::store_matrix_sync(C + (size_t)(m0 + wm * 32 + i * 16) * ldc + n0 + wn * 64 + j * 16,
                                        acc[i][j], ldc, wmma::mem_row_major);
    } else if (MODE == 2 || MODE == 3) {
        float* st = (float*)dsm;
        #pragma unroll
        for (int i = 0; i < 2; i++)
            #pragma unroll
            for (int j = 0; j < 4; j++)
                wmma::store_matrix_sync(st + (wm * 32 + i * 16) * SSTR + wn * 64 + j * 16,
                                        acc[i][j], SSTR, wmma::mem_row_major);
        __syncthreads();
        const int r = tid >> 1;
        const int c0 = (tid & 1) * 64;
        if (MODE == 2) {
            const size_t off = (size_t)(m0 + r) * ldc + (size_t)h * HD + c0;
            #pragma unroll
            for (int cc = 0; cc < 64; cc += 2)
                split2(st[r * SSTR + c0 + cc], st[r * SSTR + c0 + cc + 1],
                       Ch + off + cc, Cl + off + cc);
        } else {
            // RoPE: tile spans exactly one head (n0 % 128 == 0); pairs (2i, 2i+1)
            const float s_pos = (float)(m0 + r);
            const size_t off = (size_t)(m0 + r) * ldc + n0 + c0;
            #pragma unroll
            for (int cc = 0; cc < 64; cc += 2) {
                const int c = c0 + cc;
                const int i = c >> 1;
                float freq = __powf(500000.0f, -(float)i * (1.0f / 64.0f));
                float sn, cs; sincosf(s_pos * freq, &sn, &cs);
                float x0 = st[r * SSTR + c], x1 = st[r * SSTR + c + 1];
                split2(x0 * cs - x1 * sn, x0 * sn + x1 * cs, Ch + off + cc, Cl + off + cc);
            }
        }
    } else {
        // MODE 4: stage col-major (transpose), write vt[d, t] hi/lo
        float* st = (float*)dsm;
        #pragma unroll
        for (int i = 0; i < 2; i++)
            #pragma unroll
            for (int j = 0; j < 4; j++)
                wmma::store_matrix_sync(st + (wn * 64 + j * 16) * SSTR + wm * 32 + i * 16,
                                        acc[i][j], SSTR, wmma::mem_col_major);
        __syncthreads();
        const int d = tid >> 1;
        const int t0 = (tid & 1) * 64;
        const size_t off = (size_t)(n0 + d) * ldc + m0 + t0;
        #pragma unroll
        for (int tt = 0; tt < 64; tt += 2)
            split2(st[d * SSTR + t0 + tt], st[d * SSTR + t0 + tt + 1],
                   Ch + off + tt, Cl + off + tt);
    }
}

// ================= small kernels =================
__global__ void split_kernel(const float4* __restrict__ s, __nv_bfloat162* __restrict__ h2,
                             __nv_bfloat162* __restrict__ l2, int n4) {
    const int i0 = blockIdx.x * 1024 + threadIdx.x;
    #pragma unroll
    for (int u = 0; u < 4; u++) {
        const int i = i0 + u * 256;
        if (i >= n4) return;
        float4 v = s[i];
        bf16 a = __float2bfloat16(v.x), b = __float2bfloat16(v.y);
        bf16 c = __float2bfloat16(v.z), d = __float2bfloat16(v.w);
        h2[2*i]   = __halves2bfloat162(a, b);
        h2[2*i+1] = __halves2bfloat162(c, d);
        l2[2*i]   = __halves2bfloat162(__float2bfloat16(v.x - __bfloat162float(a)),
                                       __float2bfloat16(v.y - __bfloat162float(b)));
        l2[2*i+1] = __halves2bfloat162(__float2bfloat16(v.z - __bfloat162float(c)),
                                       __float2bfloat16(v.w - __bfloat162float(d)));
    }
}

// warp-per-row softmax: scale + causal mask inside; bf16 hi/lo probs out,
// tail zeroed to the next 128 boundary so PV runs a truncated plain GEMM.
__global__ void softmax_kernel(const float* __restrict__ scores, bf16* __restrict__ ph,
                               bf16* __restrict__ pl) {
    const int warp = threadIdx.x >> 5, lane = threadIdx.x & 31;
    const int s = blockIdx.x * 8 + warp;
    const int h = blockIdx.y;
    const float* row = scores + ((size_t)h * SEQ + s) * SEQ;
    bf16* prh = ph + ((size_t)h * SEQ + s) * SEQ;
    bf16* prl = pl + ((size_t)h * SEQ + s) * SEQ;
    const int len = s + 1;
    const int zlen = ((s >> 7) + 1) << 7;
    const float scale = 0.08838834764831845f;

    float mx = -3.402823466e38f;
    for (int t = lane; t < len; t += 32) mx = fmaxf(mx, row[t]);
    #pragma unroll
    for (int o = 16; o > 0; o >>= 1) mx = fmaxf(mx, __shfl_xor_sync(0xffffffffu, mx, o));
    mx *= scale;

    float sum = 0.f;
    for (int t = lane; t < len; t += 32) sum += __expf(row[t] * scale - mx);
    #pragma unroll
    for (int o = 16; o > 0; o >>= 1) sum += __shfl_xor_sync(0xffffffffu, sum, o);
    const float inv = 1.0f / sum;

    for (int t = lane; t < len; t += 32) {
        float p = __expf(row[t] * scale - mx) * inv;
        bf16 hh = __float2bfloat16(p);
        prh[t] = hh;
        prl[t] = __float2bfloat16(p - __bfloat162float(hh));
    }
    const bf16 z = __float2bfloat16(0.f);
    for (int t = len + lane; t < zlen; t += 32) { prh[t] = z; prl[t] = z; }
}

// ================= host =================
extern "C" void kernel_launch(void* const* d_in, const int* in_sizes, int n_in,
                              void* d_out, int out_size) {
    (void)in_sizes; (void)n_in; (void)out_size;
    const float* x  = (const float*)d_in[0];
    const float* wq = (const float*)d_in[1];
    const float* wk = (const float*)d_in[2];
    const float* wv = (const float*)d_in[3];
    const float* wo = (const float*)d_in[4];
    float* out = (float*)d_out;

    float *scores;
    bf16 *xh, *xl, *wqh, *wql, *wkh, *wkl, *wvh, *wvl, *woh, *wol;
    bf16 *qh, *ql, *kh, *kl, *vth, *vtl, *ph, *pl, *ah, *al;
    cudaGetSymbolAddress((void**)&scores, g_scores);
    cudaGetSymbolAddress((void**)&xh, g_xh);  cudaGetSymbolAddress((void**)&xl, g_xl);
    cudaGetSymbolAddress((void**)&wqh, g_wqh); cudaGetSymbolAddress((void**)&wql, g_wql);
    cudaGetSymbolAddress((void**)&wkh, g_wkh); cudaGetSymbolAddress((void**)&wkl, g_wkl);
    cudaGetSymbolAddress((void**)&wvh, g_wvh); cudaGetSymbolAddress((void**)&wvl, g_wvl);
    cudaGetSymbolAddress((void**)&woh, g_woh); cudaGetSymbolAddress((void**)&wol, g_wol);
    cudaGetSymbolAddress((void**)&qh, g_qh);  cudaGetSymbolAddress((void**)&ql, g_ql);
    cudaGetSymbolAddress((void**)&kh, g_kh);  cudaGetSymbolAddress((void**)&kl, g_kl);
    cudaGetSymbolAddress((void**)&vth, g_vth); cudaGetSymbolAddress((void**)&vtl, g_vtl);
    cudaGetSymbolAddress((void**)&ph, g_ph);  cudaGetSymbolAddress((void**)&pl, g_pl);
    cudaGetSymbolAddress((void**)&ah, g_ah);  cudaGetSymbolAddress((void**)&al, g_al);

    cudaFuncSetAttribute(gemm3_kernel<0>, cudaFuncAttributeMaxDynamicSharedMemorySize, GSMEM);
    cudaFuncSetAttribute(gemm3_kernel<1>, cudaFuncAttributeMaxDynamicSharedMemorySize, GSMEM);
    cudaFuncSetAttribute(gemm3_kernel<2>, cudaFuncAttributeMaxDynamicSharedMemorySize, GSMEM);
    cudaFuncSetAttribute(gemm3_kernel<3>, cudaFuncAttributeMaxDynamicSharedMemorySize, GSMEM);
    cudaFuncSetAttribute(gemm3_kernel<4>, cudaFuncAttributeMaxDynamicSharedMemorySize, GSMEM);

    // split inputs to bf16 hi/lo
    split_kernel<<<SEQ*DIM/4096, 256>>>((const float4*)x,  (__nv_bfloat162*)xh,  (__nv_bfloat162*)xl,  SEQ*DIM/4);
    split_kernel<<<DIM*DIM/4096, 256>>>((const float4*)wq, (__nv_bfloat162*)wqh, (__nv_bfloat162*)wql, DIM*DIM/4);
    split_kernel<<<KVD*DIM/4096, 256>>>((const float4*)wk, (__nv_bfloat162*)wkh, (__nv_bfloat162*)wkl, KVD*DIM/4);
    split_kernel<<<KVD*DIM/4096, 256>>>((const float4*)wv, (__nv_bfloat162*)wvh, (__nv_bfloat162*)wvl, KVD*DIM/4);
    split_kernel<<<DIM*DIM/4096, 256>>>((const float4*)wo, (__nv_bfloat162*)woh, (__nv_bfloat162*)wol, DIM*DIM/4);

    // projections with fused epilogues (RoPE for Q/K, transpose for V)
    gemm3_kernel<3><<<dim3(DIM/128, SEQ/128), 256, GSMEM>>>(xh, xl, wqh, wql, nullptr, qh, ql, DIM, DIM, DIM, DIM);
    gemm3_kernel<3><<<dim3(KVD/128, SEQ/128), 256, GSMEM>>>(xh, xl, wkh, wkl, nullptr, kh, kl, DIM, DIM, DIM, KVD);
    gemm3_kernel<4><<<dim3(KVD/128, SEQ/128), 256, GSMEM>>>(xh, xl, wvh, wvl, nullptr, vth, vtl, DIM, DIM, DIM, SEQ);

    // attention
    gemm3_kernel<1><<<dim3(SEQ/128, SEQ/128, NH), 256, GSMEM>>>(qh, ql, kh, kl, scores, nullptr, nullptr, HD, DIM, KVD, SEQ);
    softmax_kernel<<<dim3(SEQ/8, NH), 256>>>(scores, ph, pl);
    gemm3_kernel<2><<<dim3(1, SEQ/128, NH), 256, GSMEM>>>(ph, pl, vth, vtl, nullptr, ah, al, 0, SEQ, SEQ, DIM);

    // output projection
    gemm3_kernel<0><<<dim3(DIM/128, SEQ/128), 256, GSMEM>>>(ah, al, woh, wol, out, nullptr, nullptr, DIM, DIM, DIM, DIM);
}

// round 7
// speedup vs baseline: 1.0467x; 1.0467x over previous
#include <cuda_runtime.h>
#include <cuda_bf16.h>
#include <mma.h>
#include <stdint.h>
#include <math.h>

using namespace nvcuda;

#define SEQ 2048
#define DIM 4096
#define NH 32
#define NKV 8
#define HD 128
#define KVD (NKV*HD)   // 1024

typedef __nv_bfloat16 bf16;

// ================= scratch (no cudaMalloc allowed) =================
__device__ float g_scores[(size_t)NH * SEQ * SEQ];              // 512 MB
__device__ float g_linv[NH * SEQ];                              // per-row 1/sum
__device__ bf16 g_xh[SEQ * DIM],  g_xl[SEQ * DIM];
__device__ bf16 g_wqh[DIM * DIM], g_wql[DIM * DIM];
__device__ bf16 g_wkh[KVD * DIM], g_wkl[KVD * DIM];
__device__ bf16 g_wvh[KVD * DIM], g_wvl[KVD * DIM];
__device__ bf16 g_woh[DIM * DIM], g_wol[DIM * DIM];
__device__ bf16 g_qh[SEQ * DIM],  g_ql[SEQ * DIM];
__device__ bf16 g_kh[SEQ * KVD],  g_kl[SEQ * KVD];
__device__ bf16 g_vth[KVD * SEQ], g_vtl[KVD * SEQ];             // V transposed [d, t]
__device__ bf16 g_ph[(size_t)NH * SEQ * SEQ], g_pl[(size_t)NH * SEQ * SEQ];
__device__ bf16 g_ah[SEQ * DIM],  g_al[SEQ * DIM];

// ================= cp.async helpers =================
__device__ __forceinline__ void cpa16(uint32_t dst, const void* src) {
    unsigned long long g = (unsigned long long)__cvta_generic_to_global(src);
    asm volatile("cp.async.cg.shared.global [%0], [%1], 16;" :: "r"(dst), "l"(g) : "memory");
}
#define CPA_COMMIT() asm volatile("cp.async.commit_group;" ::: "memory")
#define CPA_WAIT(n)  asm volatile("cp.async.wait_group %0;" :: "n"(n) : "memory")

__device__ __forceinline__ void split2(float v0, float v1, bf16* ph, bf16* pl) {
    bf16 h0 = __float2bfloat16(v0), h1 = __float2bfloat16(v1);
    bf16 l0 = __float2bfloat16(v0 - __bfloat162float(h0));
    bf16 l1 = __float2bfloat16(v1 - __bfloat162float(h1));
    *(__nv_bfloat162*)ph = __halves2bfloat162(h0, h1);
    *(__nv_bfloat162*)pl = __halves2bfloat162(l0, l1);
}

// ================= 3-pass bf16 HMMA GEMM =================
// C[M,N] = Ah*Bh^T + Ah*Bl^T + Al*Bh^T   (TN, row-major, 128x128 CTA tiles)
// MODE 0: generic fp32 C.
// MODE 1: scores (per-head, triangular grid), fp32 C.
// MODE 2: PV (per-head, K truncated at diagonal, reversed m order,
//         per-row 1/l normalization), bf16 hi/lo C.
// MODE 3: projection + RoPE + bf16 hi/lo C (Q and K projections).
// MODE 4: projection + transpose + bf16 hi/lo C (V projection).
//
// smem: DOUBLE-buffered chunks of K=32.  Each chunk holds 4 tiles
// (Ah, Al, Bh, Bl), each 128 rows x 32 bf16 with row stride 40 (80B).
#define TSTRIDE 40
#define TILE_E  (128 * TSTRIDE)          // 5120 elements per tile
#define CHUNK_E (4 * TILE_E)             // 20480 elements per buffer (40KB)
#define GSMEM   (2 * CHUNK_E * 2)        // 81920 bytes (>= 67584 staging)
#define SSTR    132                      // fp32 staging stride

template<int MODE>
__global__ void __launch_bounds__(256) gemm3_kernel(
    const bf16* __restrict__ Ah, const bf16* __restrict__ Al,
    const bf16* __restrict__ Bh, const bf16* __restrict__ Bl,
    float* __restrict__ Cf, bf16* __restrict__ Ch, bf16* __restrict__ Cl,
    const float* __restrict__ Linv,
    int K, int lda, int ldb, int ldc)
{
    int m0, n0;
    if (MODE == 1) {
        // triangular decode: blockIdx.x in [0, 136)
        const int L = blockIdx.x;
        int s0i = (int)((sqrtf(8.0f * (float)L + 1.0f) - 1.0f) * 0.5f);
        while ((s0i + 1) * (s0i + 2) / 2 <= L) s0i++;
        while (s0i * (s0i + 1) / 2 > L) s0i--;
        m0 = s0i * 128;
        n0 = (L - s0i * (s0i + 1) / 2) * 128;
    } else if (MODE == 2) {
        m0 = (int)(gridDim.y - 1 - blockIdx.y) * 128;   // heavy tiles first
        n0 = blockIdx.x * 128;
    } else {
        m0 = blockIdx.y * 128;
        n0 = blockIdx.x * 128;
    }
    const int h = blockIdx.z, kvh = h >> 2;
    const int tid = threadIdx.x;
    const int warp = tid >> 5;
    const int wm = warp >> 1;           // 0..3  (32-row slice)
    const int wn = warp & 1;            // 0..1  (64-col slice)

    size_t aoff, boff, coff = 0;
    int kLen = K;
    if (MODE == 1)      { aoff = (size_t)m0 * lda + (size_t)h * HD;        boff = (size_t)n0 * ldb + (size_t)kvh * HD;
                          coff = (size_t)h * SEQ * SEQ; }
    else if (MODE == 2) { aoff = (size_t)h * SEQ * SEQ + (size_t)m0 * lda; boff = (size_t)(kvh * HD) * ldb;
                          kLen = m0 + 128; }
    else                { aoff = (size_t)m0 * lda;                         boff = (size_t)n0 * ldb; }
    const bf16* pAh = Ah + aoff; const bf16* pAl = Al + aoff;
    const bf16* pBh = Bh + boff; const bf16* pBl = Bl + boff;

    extern __shared__ __align__(16) char dsm[];
    bf16* smem = (bf16*)dsm;
    const uint32_t sm_u32 = (uint32_t)__cvta_generic_to_shared(dsm);

    wmma::fragment<wmma::accumulator, 16, 16, 16, float> acc[2][4];
    #pragma unroll
    for (int i = 0; i < 2; i++)
        #pragma unroll
        for (int j = 0; j < 4; j++) wmma::fill_fragment(acc[i][j], 0.0f);

    const int NC = kLen >> 5;   // K chunks of 32  (always >= 4 here)

    const int lrow = tid >> 1;
    const int lseg = (tid & 1) * 2;

    auto load_chunk = [&](int buf, int ko) {
        const uint32_t b = sm_u32 + buf * CHUNK_E * 2;
        const uint32_t soff = (uint32_t)(lrow * TSTRIDE + lseg * 8) * 2;
        const bf16* srcs[4] = { pAh + ko, pAl + ko, pBh + ko, pBl + ko };
        const int lds[4] = { lda, lda, ldb, ldb };
        #pragma unroll
        for (int t = 0; t < 4; t++) {
            const bf16* g = srcs[t] + (size_t)lrow * lds[t] + lseg * 8;
            const uint32_t d = b + t * TILE_E * 2 + soff;
            cpa16(d, g);
            cpa16(d + 16, g + 8);
        }
    };

    load_chunk(0, 0);
    CPA_COMMIT();

    for (int c = 0; c < NC; ++c) {
        if (c + 1 < NC) {
            load_chunk((c + 1) & 1, (c + 1) << 5);
            CPA_COMMIT();
            CPA_WAIT(1);
        } else {
            CPA_WAIT(0);
        }
        __syncthreads();

        const bf16* sb = smem + (c & 1) * CHUNK_E;
        const bf16* sAh = sb;
        const bf16* sAl = sb + TILE_E;
        const bf16* sBh = sb + 2 * TILE_E;
        const bf16* sBl = sb + 3 * TILE_E;

        #pragma unroll
        for (int kk = 0; kk < 32; kk += 16) {
            wmma::fragment<wmma::matrix_a, 16, 16, 16, bf16, wmma::row_major> ah[2], al[2];
            wmma::fragment<wmma::matrix_b, 16, 16, 16, bf16, wmma::col_major> bh[4], bl[4];
            #pragma unroll
            for (int i = 0; i < 2; i++) {
                wmma::load_matrix_sync(ah[i], sAh + (wm * 32 + i * 16) * TSTRIDE + kk, TSTRIDE);
                wmma::load_matrix_sync(al[i], sAl + (wm * 32 + i * 16) * TSTRIDE + kk, TSTRIDE);
            }
            #pragma unroll
            for (int j = 0; j < 4; j++) {
                wmma::load_matrix_sync(bh[j], sBh + (wn * 64 + j * 16) * TSTRIDE + kk, TSTRIDE);
                wmma::load_matrix_sync(bl[j], sBl + (wn * 64 + j * 16) * TSTRIDE + kk, TSTRIDE);
            }
            #pragma unroll
            for (int i = 0; i < 2; i++)
                #pragma unroll
                for (int j = 0; j < 4; j++) {
                    wmma::mma_sync(acc[i][j], ah[i], bh[j], acc[i][j]);
                    wmma::mma_sync(acc[i][j], ah[i], bl[j], acc[i][j]);
                    wmma::mma_sync(acc[i][j], al[i], bh[j], acc[i][j]);
                }
        }
        __syncthreads();
    }

    // ===================== epilogues =====================
    if (MODE == 0 || MODE == 1) {
        float* C = Cf + coff;
        #pragma unroll
        for (int i = 0; i < 2; i++)
            #pragma unroll
            for (int j = 0; j < 4; j++)
                wmma::store_matrix_sync(C + (size_t)(m0 + wm * 32 + i * 16) * ldc + n0 + wn * 64 + j * 16,
                                        acc[i][j], ldc, wmma::mem_row_major);
    } else if (MODE == 2 || MODE == 3) {
        float* st = (float*)dsm;
        #pragma unroll
        for (int i = 0; i < 2; i++)
            #pragma unroll
            for (int j = 0; j < 4; j++)
                wmma::store_matrix_sync(st + (wm * 32 + i * 16) * SSTR + wn * 64 + j * 16,
                                        acc[i][j], SSTR, wmma::mem_row_major);
        __syncthreads();
        const int r = tid >> 1;
        const int c0 = (tid & 1) * 64;
        if (MODE == 2) {
            const float sc = Linv[h * SEQ + m0 + r];   // fold softmax normalization here
            const size_t off = (size_t)(m0 + r) * ldc + (size_t)h * HD + c0;
            #pragma unroll
            for (int cc = 0; cc < 64; cc += 2)
                split2(st[r * SSTR + c0 + cc] * sc, st[r * SSTR + c0 + cc + 1] * sc,
                       Ch + off + cc, Cl + off + cc);
        } else {
            // RoPE: tile spans exactly one head (n0 % 128 == 0); pairs (2i, 2i+1)
            const float s_pos = (float)(m0 + r);
            const size_t off = (size_t)(m0 + r) * ldc + n0 + c0;
            #pragma unroll
            for (int cc = 0; cc < 64; cc += 2) {
                const int c = c0 + cc;
                const int i = c >> 1;
                float freq = __powf(500000.0f, -(float)i * (1.0f / 64.0f));
                float sn, cs; sincosf(s_pos * freq, &sn, &cs);
                float x0 = st[r * SSTR + c], x1 = st[r * SSTR + c + 1];
                split2(x0 * cs - x1 * sn, x0 * sn + x1 * cs, Ch + off + cc, Cl + off + cc);
            }
        }
    } else {
        // MODE 4: stage col-major (transpose), write vt[d, t] hi/lo
        float* st = (float*)dsm;
        #pragma unroll
        for (int i = 0; i < 2; i++)
            #pragma unroll
            for (int j = 0; j < 4; j++)
                wmma::store_matrix_sync(st + (wn * 64 + j * 16) * SSTR + wm * 32 + i * 16,
                                        acc[i][j], SSTR, wmma::mem_col_major);
        __syncthreads();
        const int d = tid >> 1;
        const int t0 = (tid & 1) * 64;
        const size_t off = (size_t)(n0 + d) * ldc + m0 + t0;
        #pragma unroll
        for (int tt = 0; tt < 64; tt += 2)
            split2(st[d * SSTR + t0 + tt], st[d * SSTR + t0 + tt + 1],
                   Ch + off + tt, Cl + off + tt);
    }
}

// ================= small kernels =================
__global__ void split_kernel(const float4* __restrict__ s, __nv_bfloat162* __restrict__ h2,
                             __nv_bfloat162* __restrict__ l2, int n4) {
    const int i0 = blockIdx.x * 1024 + threadIdx.x;
    #pragma unroll
    for (int u = 0; u < 4; u++) {
        const int i = i0 + u * 256;
        if (i >= n4) return;
        float4 v = s[i];
        bf16 a = __float2bfloat16(v.x), b = __float2bfloat16(v.y);
        bf16 c = __float2bfloat16(v.z), d = __float2bfloat16(v.w);
        h2[2*i]   = __halves2bfloat162(a, b);
        h2[2*i+1] = __halves2bfloat162(c, d);
        l2[2*i]   = __halves2bfloat162(__float2bfloat16(v.x - __bfloat162float(a)),
                                       __float2bfloat16(v.y - __bfloat162float(b)));
        l2[2*i+1] = __halves2bfloat162(__float2bfloat16(v.z - __bfloat162float(c)),
                                       __float2bfloat16(v.w - __bfloat162float(d)));
    }
}

// warp-per-row softmax, EXP-ONCE: caches the scaled row in smem, computes max,
// then a single exp pass writing UNNORMALIZED e-values (bf16 hi/lo) and 1/sum.
// Tail zeroed to the next 128 boundary so PV runs a truncated plain GEMM.
// PV epilogue multiplies rows by linv.
__global__ void softmax_kernel(const float* __restrict__ scores, bf16* __restrict__ ph,
                               bf16* __restrict__ pl, float* __restrict__ linv) {
    extern __shared__ float cache[];   // 8 warps x 2048 floats = 64KB
    const int warp = threadIdx.x >> 5, lane = threadIdx.x & 31;
    const int s = blockIdx.x * 8 + warp;
    const int h = blockIdx.y;
    const float* row = scores + ((size_t)h * SEQ + s) * SEQ;
    bf16* prh = ph + ((size_t)h * SEQ + s) * SEQ;
    bf16* prl = pl + ((size_t)h * SEQ + s) * SEQ;
    float* cr = cache + warp * SEQ;
    const int len = s + 1;
    const int zlen = ((s >> 7) + 1) << 7;
    const float scale = 0.08838834764831845f;

    float mx = -3.402823466e38f;
    for (int t = lane; t < len; t += 32) {
        float v = row[t] * scale;
        cr[t] = v;
        mx = fmaxf(mx, v);
    }
    #pragma unroll
    for (int o = 16; o > 0; o >>= 1) mx = fmaxf(mx, __shfl_xor_sync(0xffffffffu, mx, o));

    float sum = 0.f;
    for (int t = lane; t < len; t += 32) {
        float e = __expf(cr[t] - mx);
        sum += e;
        bf16 hh = __float2bfloat16(e);
        prh[t] = hh;
        prl[t] = __float2bfloat16(e - __bfloat162float(hh));
    }
    #pragma unroll
    for (int o = 16; o > 0; o >>= 1) sum += __shfl_xor_sync(0xffffffffu, sum, o);
    if (lane == 0) linv[h * SEQ + s] = 1.0f / sum;

    const bf16 z = __float2bfloat16(0.f);
    for (int t = len + lane; t < zlen; t += 32) { prh[t] = z; prl[t] = z; }
}

// ================= host =================
extern "C" void kernel_launch(void* const* d_in, const int* in_sizes, int n_in,
                              void* d_out, int out_size) {
    (void)in_sizes; (void)n_in; (void)out_size;
    const float* x  = (const float*)d_in[0];
    const float* wq = (const float*)d_in[1];
    const float* wk = (const float*)d_in[2];
    const float* wv = (const float*)d_in[3];
    const float* wo = (const float*)d_in[4];
    float* out = (float*)d_out;

    float *scores, *linv;
    bf16 *xh, *xl, *wqh, *wql, *wkh, *wkl, *wvh, *wvl, *woh, *wol;
    bf16 *qh, *ql, *kh, *kl, *vth, *vtl, *ph, *pl, *ah, *al;
    cudaGetSymbolAddress((void**)&scores, g_scores);
    cudaGetSymbolAddress((void**)&linv, g_linv);
    cudaGetSymbolAddress((void**)&xh, g_xh);  cudaGetSymbolAddress((void**)&xl, g_xl);
    cudaGetSymbolAddress((void**)&wqh, g_wqh); cudaGetSymbolAddress((void**)&wql, g_wql);
    cudaGetSymbolAddress((void**)&wkh, g_wkh); cudaGetSymbolAddress((void**)&wkl, g_wkl);
    cudaGetSymbolAddress((void**)&wvh, g_wvh); cudaGetSymbolAddress((void**)&wvl, g_wvl);
    cudaGetSymbolAddress((void**)&woh, g_woh); cudaGetSymbolAddress((void**)&wol, g_wol);
    cudaGetSymbolAddress((void**)&qh, g_qh);  cudaGetSymbolAddress((void**)&ql, g_ql);
    cudaGetSymbolAddress((void**)&kh, g_kh);  cudaGetSymbolAddress((void**)&kl, g_kl);
    cudaGetSymbolAddress((void**)&vth, g_vth); cudaGetSymbolAddress((void**)&vtl, g_vtl);
    cudaGetSymbolAddress((void**)&ph, g_ph);  cudaGetSymbolAddress((void**)&pl, g_pl);
    cudaGetSymbolAddress((void**)&ah, g_ah);  cudaGetSymbolAddress((void**)&al, g_al);

    cudaFuncSetAttribute(gemm3_kernel<0>, cudaFuncAttributeMaxDynamicSharedMemorySize, GSMEM);
    cudaFuncSetAttribute(gemm3_kernel<1>, cudaFuncAttributeMaxDynamicSharedMemorySize, GSMEM);
    cudaFuncSetAttribute(gemm3_kernel<2>, cudaFuncAttributeMaxDynamicSharedMemorySize, GSMEM);
    cudaFuncSetAttribute(gemm3_kernel<3>, cudaFuncAttributeMaxDynamicSharedMemorySize, GSMEM);
    cudaFuncSetAttribute(gemm3_kernel<4>, cudaFuncAttributeMaxDynamicSharedMemorySize, GSMEM);
    cudaFuncSetAttribute(softmax_kernel, cudaFuncAttributeMaxDynamicSharedMemorySize, 8 * SEQ * 4);

    // split inputs to bf16 hi/lo
    split_kernel<<<SEQ*DIM/4096, 256>>>((const float4*)x,  (__nv_bfloat162*)xh,  (__nv_bfloat162*)xl,  SEQ*DIM/4);
    split_kernel<<<DIM*DIM/4096, 256>>>((const float4*)wq, (__nv_bfloat162*)wqh, (__nv_bfloat162*)wql, DIM*DIM/4);
    split_kernel<<<KVD*DIM/4096, 256>>>((const float4*)wk, (__nv_bfloat162*)wkh, (__nv_bfloat162*)wkl, KVD*DIM/4);
    split_kernel<<<KVD*DIM/4096, 256>>>((const float4*)wv, (__nv_bfloat162*)wvh, (__nv_bfloat162*)wvl, KVD*DIM/4);
    split_kernel<<<DIM*DIM/4096, 256>>>((const float4*)wo, (__nv_bfloat162*)woh, (__nv_bfloat162*)wol, DIM*DIM/4);

    // projections with fused epilogues (RoPE for Q/K, transpose for V)
    gemm3_kernel<3><<<dim3(DIM/128, SEQ/128), 256, GSMEM>>>(xh, xl, wqh, wql, nullptr, qh, ql, nullptr, DIM, DIM, DIM, DIM);
    gemm3_kernel<3><<<dim3(KVD/128, SEQ/128), 256, GSMEM>>>(xh, xl, wkh, wkl, nullptr, kh, kl, nullptr, DIM, DIM, DIM, KVD);
    gemm3_kernel<4><<<dim3(KVD/128, SEQ/128), 256, GSMEM>>>(xh, xl, wvh, wvl, nullptr, vth, vtl, nullptr, DIM, DIM, DIM, SEQ);

    // attention
    gemm3_kernel<1><<<dim3(136, 1, NH), 256, GSMEM>>>(qh, ql, kh, kl, scores, nullptr, nullptr, nullptr, HD, DIM, KVD, SEQ);
    softmax_kernel<<<dim3(SEQ/8, NH), 256, 8*SEQ*4>>>(scores, ph, pl, linv);
    gemm3_kernel<2><<<dim3(1, SEQ/128, NH), 256, GSMEM>>>(ph, pl, vth, vtl, nullptr, ah, al, linv, 0, SEQ, SEQ, DIM);

    // output projection
    gemm3_kernel<0><<<dim3(DIM/128, SEQ/128), 256, GSMEM>>>(ah, al, woh, wol, out, nullptr, nullptr, nullptr, DIM, DIM, DIM, DIM);
}